// round 3
// baseline (speedup 1.0000x reference)
#include <cuda_runtime.h>
#include <cuda_fp16.h>
#include <cstdint>

#define HH 1024
#define WW 1024
#define XV 4      // output pixels per thread (one float4 store)
#define RWS 16    // output rows per thread strip

// One converted input row: aligned half2 pairs A[m]=(v[2m],v[2m+1]) and
// shifted pairs S[m]=(v[2m+1],v[2m+2]) over the 8-float window v = cols x0-2..x0+5.
struct Row {
    __half2 A[4];
    __half2 S[3];
};

__device__ __forceinline__ void load_row(Row& R, const float* __restrict__ ip,
                                         int y, int x0, bool interior) {
    float v[8];
    const float INFv = __int_as_float(0x7f800000);
    if (y < 0 || y >= HH) {
#pragma unroll
        for (int m = 0; m < 8; ++m) v[m] = INFv;
    } else if (interior) {
        const float* base = ip + (size_t)y * WW + x0;
        float2 p0 = *reinterpret_cast<const float2*>(base - 2);
        float4 p1 = *reinterpret_cast<const float4*>(base);
        float2 p2 = *reinterpret_cast<const float2*>(base + 4);
        v[0] = p0.x; v[1] = p0.y;
        v[2] = p1.x; v[3] = p1.y; v[4] = p1.z; v[5] = p1.w;
        v[6] = p2.x; v[7] = p2.y;
    } else {
        const float* base = ip + (size_t)y * WW;
#pragma unroll
        for (int m = 0; m < 8; ++m) {
            int col = x0 - 2 + m;
            v[m] = (col >= 0 && col < WW) ? base[col] : INFv;
        }
    }
#pragma unroll
    for (int m = 0; m < 4; ++m) R.A[m] = __floats2half2_rn(v[2 * m], v[2 * m + 1]);
#pragma unroll
    for (int m = 0; m < 3; ++m) R.S[m] = __floats2half2_rn(v[2 * m + 1], v[2 * m + 2]);
}

__global__ __launch_bounds__(128, 4)
void erosion5x5_h2_kernel(const float* __restrict__ img,
                          const float* __restrict__ filt,
                          float* __restrict__ out) {
    const int x0 = (blockIdx.x * blockDim.x + threadIdx.x) * XV;
    const int y0 = blockIdx.y * RWS;
    const size_t plane = (size_t)blockIdx.z * (size_t)HH * (size_t)WW;
    const float* ip = img + plane;
    float* op = out + plane;

    const bool interior = (x0 >= 2) && (x0 + 6 <= WW);

    // Broadcast filter taps as half2 (L1-hot loads, hoisted by full unroll)
    __half2 hf[25];
#pragma unroll
    for (int t = 0; t < 25; ++t) hf[t] = __float2half2_rn(filt[t]);

    // Rolling 5-row window: slot k%5 holds input row y0+k-2 (fully unrolled -> static)
    Row W[5];
#pragma unroll
    for (int k = 0; k < 4; ++k)
        load_row(W[k], ip, y0 + k - 2, x0, interior);

#pragma unroll
    for (int r = 0; r < RWS; ++r) {
        load_row(W[(r + 4) % 5], ip, y0 + r + 2, x0, interior);

        __half2 a0, a1;  // packed accumulators: pixels (0,1) and (2,3)
        {
            const Row& R0 = W[r % 5];
            const __half2 f0 = hf[0];
            a0 = __hsub2(R0.A[0], f0);
            a1 = __hsub2(R0.A[1], f0);
        }
#pragma unroll
        for (int i = 0; i < 5; ++i) {
            const Row& R = W[(r + i) % 5];
#pragma unroll
            for (int j = 0; j < 5; ++j) {
                if (i == 0 && j == 0) continue;
                const __half2 f = hf[i * 5 + j];
                // pixel pair (c,c+1) at tap j reads cols (c+j, c+j+1) of v:
                //  c=0 -> index j ; c=2 -> index j+2
                __half2 p0, p1;
                if ((j & 1) == 0) {
                    p0 = R.A[j / 2];
                    p1 = R.A[j / 2 + 1];
                } else {
                    p0 = R.S[(j - 1) / 2];
                    p1 = R.S[(j - 1) / 2 + 1];
                }
                a0 = __hmin2(a0, __hsub2(p0, f));
                a1 = __hmin2(a1, __hsub2(p1, f));
            }
        }

        float2 lo = __half22float2(a0);
        float2 hi = __half22float2(a1);
        float4 o = make_float4(lo.x, lo.y, hi.x, hi.y);
        *reinterpret_cast<float4*>(op + (size_t)(y0 + r) * WW + x0) = o;
    }
}

extern "C" void kernel_launch(void* const* d_in, const int* in_sizes, int n_in,
                              void* d_out, int out_size) {
    const float* image = (const float*)d_in[0];
    const float* filt  = (const float*)d_in[1];
    float* out = (float*)d_out;

    const int planes = in_sizes[0] / (HH * WW);  // 96

    dim3 block(128, 1, 1);
    dim3 grid(WW / (128 * XV), HH / RWS, planes);  // (2, 64, 96)
    erosion5x5_h2_kernel<<<grid, block>>>(image, filt, out);
}